// round 3
// baseline (speedup 1.0000x reference)
#include <cuda_runtime.h>
#include <math.h>
#include <stdint.h>

#define N_QUBITS 8
#define HW 65536           // 256*256
#define CC 64              // channels
#define OO 64              // output channels
#define BB 16              // batch
#define PIF 3.14159265358979323846f

// ---------------- device scratch (no allocations allowed) ----------------
__device__ float g_xglobal[BB * CC];   // per (b,c) spatial mean
__device__ float g_add[BB * OO];       // conv_b[o] + gate_b * g_b[o]

// ---------------- f32x2 helpers (packed dual-FMA) ------------------------
__device__ __forceinline__ void ffma2(unsigned long long& d,
                                      unsigned long long a,
                                      unsigned long long b) {
    asm("fma.rn.f32x2 %0, %1, %2, %0;" : "+l"(d) : "l"(a), "l"(b));
}
__device__ __forceinline__ unsigned long long pack2(float x, float y) {
    unsigned long long r;
    asm("mov.b64 %0, {%1, %2};" : "=l"(r) : "f"(x), "f"(y));
    return r;
}
__device__ __forceinline__ float2 unpack2(unsigned long long v) {
    float2 f;
    asm("mov.b64 {%0, %1}, %2;" : "=f"(f.x), "=f"(f.y) : "l"(v));
    return f;
}

// ---------------- cp.async helpers ---------------------------------------
__device__ __forceinline__ void cp_async16(uint32_t s, const float* g) {
    asm volatile("cp.async.cg.shared.global [%0], [%1], 16;\n"
                 :: "r"(s), "l"(__cvta_generic_to_global(g)));
}
__device__ __forceinline__ void cp_commit() {
    asm volatile("cp.async.commit_group;\n");
}
template <int N>
__device__ __forceinline__ void cp_wait() {
    asm volatile("cp.async.wait_group %0;\n" :: "n"(N));
}

// ================= K1: per-(b,c) spatial mean =============================
__global__ void k_reduce(const float* __restrict__ x) {
    const float4* p = reinterpret_cast<const float4*>(x + (size_t)blockIdx.x * HW);
    float s = 0.0f;
    #pragma unroll 8
    for (int i = threadIdx.x; i < HW / 4; i += 256) {
        float4 v = p[i];
        s += (v.x + v.y) + (v.z + v.w);
    }
    #pragma unroll
    for (int o = 16; o; o >>= 1) s += __shfl_xor_sync(0xffffffffu, s, o);
    __shared__ float ws[8];
    if ((threadIdx.x & 31) == 0) ws[threadIdx.x >> 5] = s;
    __syncthreads();
    if (threadIdx.x == 0) {
        float t = 0.0f;
        #pragma unroll
        for (int w = 0; w < 8; w++) t += ws[w];
        g_xglobal[blockIdx.x] = t * (1.0f / (float)HW);
    }
}

// ================= K2: quantum circuit + gate + MLP =======================
__global__ void k_small(const float* __restrict__ cw,
                        const float* __restrict__ qw,
                        const float* __restrict__ w1,
                        const float* __restrict__ b1,
                        const float* __restrict__ w2,
                        const float* __restrict__ b2,
                        const float* __restrict__ conv_b,
                        float* __restrict__ out,
                        int out_size) {
    __shared__ float sh_h[BB][OO];
    int b = threadIdx.x >> 5;
    int lane = threadIdx.x & 31;

    float xq[N_QUBITS];
    #pragma unroll
    for (int p = 0; p < 4; p++) {
        int ia = 2 * p, ib = 2 * p + 1;
        float in_a = g_xglobal[b * CC + ia] * cw[ia];
        float in_b = g_xglobal[b * CC + ib] * cw[ib];
        float ta = PIF * in_a + qw[ia];
        float tb = PIF * in_b + qw[ib];
        float sa, ca, sb, cb;
        sincosf(ta * 0.5f, &sa, &ca);
        sincosf(tb * 0.5f, &sb, &cb);
        float psi00 = ca * cb, psi01 = ca * sb, psi10 = sa * sb, psi11 = sa * cb;
        float shA, chA, shB, chB;
        sincosf(qw[8 + ia] * 0.5f, &shA, &chA);
        sincosf(qw[8 + ib] * 0.5f, &shB, &chB);
        float m00 = chA * psi00 - shA * psi10, m01 = chA * psi01 - shA * psi11;
        float m10 = shA * psi00 + chA * psi10, m11 = shA * psi01 + chA * psi11;
        float q00 = m00 * chB - m01 * shB, q01 = m00 * shB + m01 * chB;
        float q10 = m10 * chB - m11 * shB, q11 = m10 * shB + m11 * chB;
        float p00 = q00 * q00, p01 = q01 * q01, p10 = q10 * q10, p11 = q11 * q11;
        xq[ia] = (p00 + p01) - (p10 + p11);
        xq[ib] = (p00 + p10) - (p01 + p11);
    }
    float ss = 0.0f;
    #pragma unroll
    for (int i = 0; i < N_QUBITS; i++) ss += xq[i] * xq[i];
    float strength = sqrtf(ss);
    float gate = 1.0f / (1.0f + expf(-(strength - 0.05f)));

    #pragma unroll
    for (int rep = 0; rep < 2; rep++) {
        int j = lane + rep * 32;
        float hv = b1[j];
        #pragma unroll
        for (int i = 0; i < N_QUBITS; i++) hv += xq[i] * w1[j * N_QUBITS + i];
        sh_h[b][j] = fmaxf(hv, 0.0f);
    }
    __syncwarp();

    #pragma unroll
    for (int rep = 0; rep < 2; rep++) {
        int o = lane + rep * 32;
        float gv = b2[o];
        #pragma unroll 8
        for (int j = 0; j < OO; j++) gv += sh_h[b][j] * w2[o * OO + j];
        g_add[b * OO + o] = conv_b[o] + gate * gv;
    }

    const long long base = (long long)BB * OO * HW;
    if ((long long)out_size >= base + BB * N_QUBITS + BB) {
        if (lane < N_QUBITS) out[base + b * N_QUBITS + lane] = xq[lane];
        if (lane == 0) out[base + BB * N_QUBITS + b] = strength;
    }
}

// ================= K3: 64x64 1x1-conv GEMM ================================
// SMEM-staged, cp.async double-buffered, packed f32x2 math.
// grid = (HW/256, B), 256 threads: 4 o-groups (16 o) x 64 px-groups (4 px).
// SMEM: weights dup-packed (32 KB) + x stages 2 x 8c x 256px (16 KB) = 48 KB.
#define CHUNK 8                       // channels per stage
#define NCHUNK (CC / CHUNK)           // 8

__global__ void __launch_bounds__(256, 2)
k_conv(const float* __restrict__ x, const float* __restrict__ conv_w,
       float* __restrict__ out) {
    __shared__ __align__(16) unsigned long long smem_w[CC * OO];     // 32 KB
    __shared__ __align__(16) float smem_x[2][CHUNK][256];            // 16 KB

    const int tid = threadIdx.x;

    // dup-packed weights: smem_w[c*64+o] = (w,w)
    #pragma unroll
    for (int e = tid; e < CC * OO; e += 256) {
        int c = e >> 6, o = e & 63;
        float w = conv_w[o * CC + c];
        smem_w[c * OO + o] = pack2(w, w);
    }

    const int og = tid >> 6;    // 0..3  -> o = og*16 .. og*16+15
    const int pg = tid & 63;    // 0..63 -> px = pg*4 .. pg*4+3
    const int b = blockIdx.y;
    const int px0 = blockIdx.x * 256;

    const float* xb = x + (size_t)b * CC * HW + px0;

    // cp.async staging map: 512 x 16B per stage; idx -> (ci, 16B-slot)
    const int ld_ci0 = tid >> 6;           // rows 0..3   (idx = tid)
    const int ld_sl0 = tid & 63;
    const int ld_ci1 = 4 + (tid >> 6);     // rows 4..7   (idx = tid+256)
    const int ld_sl1 = tid & 63;

    uint32_t sx_base = (uint32_t)__cvta_generic_to_shared(&smem_x[0][0][0]);

    auto prefetch = [&](int chunk, int stage) {
        uint32_t sdst = sx_base + stage * (CHUNK * 256 * 4);
        const float* g0 = xb + (size_t)(chunk * CHUNK + ld_ci0) * HW + ld_sl0 * 4;
        const float* g1 = xb + (size_t)(chunk * CHUNK + ld_ci1) * HW + ld_sl1 * 4;
        cp_async16(sdst + (ld_ci0 * 256 + ld_sl0 * 4) * 4, g0);
        cp_async16(sdst + (ld_ci1 * 256 + ld_sl1 * 4) * 4, g1);
        cp_commit();
    };

    unsigned long long acc[32];
    #pragma unroll
    for (int i = 0; i < 32; i++) acc[i] = 0ull;

    prefetch(0, 0);
    __syncthreads();   // weights ready (also orders stage-0 usage vs fill loop)

    #pragma unroll 1
    for (int k = 0; k < NCHUNK; k++) {
        const int stage = k & 1;
        if (k + 1 < NCHUNK) {
            prefetch(k + 1, stage ^ 1);
            cp_wait<1>();
        } else {
            cp_wait<0>();
        }
        __syncthreads();

        const float* xrow = &smem_x[stage][0][0];
        #pragma unroll
        for (int ci = 0; ci < CHUNK; ci++) {
            ulonglong2 xv = *reinterpret_cast<const ulonglong2*>(xrow + ci * 256 + pg * 4);
            const ulonglong2* wr =
                reinterpret_cast<const ulonglong2*>(smem_w + (k * CHUNK + ci) * OO) + og * 8;
            #pragma unroll
            for (int j = 0; j < 8; j++) {
                ulonglong2 wv = wr[j];                 // o pair (2j, 2j+1), dup-packed
                ffma2(acc[4 * j + 0], wv.x, xv.x);
                ffma2(acc[4 * j + 1], wv.x, xv.y);
                ffma2(acc[4 * j + 2], wv.y, xv.x);
                ffma2(acc[4 * j + 3], wv.y, xv.y);
            }
        }
        __syncthreads();   // all reads of this stage done before it is refilled
    }

    float* ob = out + ((size_t)b * OO + og * 16) * HW + px0 + pg * 4;
    const float* ap = g_add + b * OO + og * 16;
    #pragma unroll
    for (int o2 = 0; o2 < 16; o2++) {
        float a = ap[o2];
        int j = o2 >> 1, hi = o2 & 1;
        float2 p01 = unpack2(acc[4 * j + 2 * hi + 0]);
        float2 p23 = unpack2(acc[4 * j + 2 * hi + 1]);
        float4 r = make_float4(p01.x + a, p01.y + a, p23.x + a, p23.y + a);
        *reinterpret_cast<float4*>(ob + (size_t)o2 * HW) = r;
    }
}

// ================= launch =================================================
extern "C" void kernel_launch(void* const* d_in, const int* in_sizes, int n_in,
                              void* d_out, int out_size) {
    const float* x       = (const float*)d_in[0];
    const float* cw      = (const float*)d_in[1];
    const float* qw      = (const float*)d_in[2];
    const float* w1      = (const float*)d_in[3];
    const float* b1      = (const float*)d_in[4];
    const float* w2      = (const float*)d_in[5];
    const float* b2      = (const float*)d_in[6];
    const float* conv_w  = (const float*)d_in[7];
    const float* conv_b  = (const float*)d_in[8];
    float* out = (float*)d_out;

    k_reduce<<<BB * CC, 256>>>(x);
    k_small<<<1, BB * 32>>>(cw, qw, w1, b1, w2, b2, conv_b, out, out_size);
    k_conv<<<dim3(HW / 256, BB), 256>>>(x, conv_w, out);
}

// round 5
// speedup vs baseline: 1.6610x; 1.6610x over previous
#include <cuda_runtime.h>
#include <math.h>
#include <stdint.h>

#define HW 65536
#define CC 64
#define OO 64
#define BB 16
#define NQ 8
#define PIF 3.14159265358979323846f
#define NTILE (BB * (HW / 128))   // 8192 tiles of 128 px
#define GRID_CONV 296

__device__ float g_xg[BB * NQ];
__device__ float g_add[BB * OO];
__device__ int   g_cnt;

// ---------------- helpers ----------------
__device__ __forceinline__ uint32_t cvt_tf32(float f) {
    uint32_t r; asm("cvt.rna.tf32.f32 %0, %1;" : "=r"(r) : "f"(f)); return r;
}
__device__ __forceinline__ void cp_async16(uint32_t s, const float* g) {
    asm volatile("cp.async.cg.shared.global [%0], [%1], 16;\n"
                 :: "r"(s), "l"(__cvta_generic_to_global(g)));
}
__device__ __forceinline__ void cp_commit() { asm volatile("cp.async.commit_group;\n"); }
template <int N> __device__ __forceinline__ void cp_wait() {
    asm volatile("cp.async.wait_group %0;\n" :: "n"(N));
}
// m16n8k8 tf32 MMA (sm_80+ baseline PTX; maps to HMMA on sm_103)
__device__ __forceinline__ void mma8(float* c, const uint32_t* a, uint32_t b0, uint32_t b1) {
    asm volatile("mma.sync.aligned.m16n8k8.row.col.f32.tf32.tf32.f32 "
                 "{%0,%1,%2,%3}, {%4,%5,%6,%7}, {%8,%9}, {%0,%1,%2,%3};"
                 : "+f"(c[0]), "+f"(c[1]), "+f"(c[2]), "+f"(c[3])
                 : "r"(a[0]), "r"(a[1]), "r"(a[2]), "r"(a[3]), "r"(b0), "r"(b1));
}

// ============ K_PRE: 8-channel means + quantum + gate + MLP (fused) ========
__global__ void k_pre(const float* __restrict__ x,
                      const float* __restrict__ cw, const float* __restrict__ qw,
                      const float* __restrict__ w1, const float* __restrict__ b1,
                      const float* __restrict__ w2, const float* __restrict__ b2,
                      const float* __restrict__ conv_b,
                      float* __restrict__ out, int out_size) {
    const int tid = threadIdx.x, bid = blockIdx.x;      // bid = b*8 + q
    const float4* p = reinterpret_cast<const float4*>(
        x + ((size_t)(bid >> 3) * CC + (bid & 7)) * HW);
    float s = 0.0f;
    #pragma unroll 8
    for (int i = tid; i < HW / 4; i += 256) {
        float4 v = p[i];
        s += (v.x + v.y) + (v.z + v.w);
    }
    #pragma unroll
    for (int o = 16; o; o >>= 1) s += __shfl_xor_sync(0xffffffffu, s, o);
    __shared__ float ws[8];
    __shared__ int s_last;
    __shared__ float sh_h[BB][OO];
    if ((tid & 31) == 0) ws[tid >> 5] = s;
    __syncthreads();
    if (tid == 0) {
        float t = 0.0f;
        #pragma unroll
        for (int w = 0; w < 8; w++) t += ws[w];
        g_xg[bid] = t * (1.0f / (float)HW);
        __threadfence();
        s_last = (atomicAdd(&g_cnt, 1) == BB * NQ - 1) ? 1 : 0;
    }
    __syncthreads();
    if (!s_last) return;
    __threadfence();

    const int wid = tid >> 5, lane = tid & 31;
    for (int rep = 0; rep < 2; rep++) {
        const int b = wid + rep * 8;
        float xq[NQ];
        #pragma unroll
        for (int pr = 0; pr < 4; pr++) {
            int ia = 2 * pr, ib = 2 * pr + 1;
            float ta = PIF * (g_xg[b * 8 + ia] * cw[ia]) + qw[ia];
            float tb = PIF * (g_xg[b * 8 + ib] * cw[ib]) + qw[ib];
            float sa, ca, sb, cb;
            sincosf(ta * 0.5f, &sa, &ca);
            sincosf(tb * 0.5f, &sb, &cb);
            float psi00 = ca * cb, psi01 = ca * sb, psi10 = sa * sb, psi11 = sa * cb;
            float shA, chA, shB, chB;
            sincosf(qw[8 + ia] * 0.5f, &shA, &chA);
            sincosf(qw[8 + ib] * 0.5f, &shB, &chB);
            float m00 = chA * psi00 - shA * psi10, m01 = chA * psi01 - shA * psi11;
            float m10 = shA * psi00 + chA * psi10, m11 = shA * psi01 + chA * psi11;
            float q00 = m00 * chB - m01 * shB, q01 = m00 * shB + m01 * chB;
            float q10 = m10 * chB - m11 * shB, q11 = m10 * shB + m11 * chB;
            float p00 = q00 * q00, p01 = q01 * q01, p10 = q10 * q10, p11 = q11 * q11;
            xq[ia] = (p00 + p01) - (p10 + p11);
            xq[ib] = (p00 + p10) - (p01 + p11);
        }
        float ss = 0.0f;
        #pragma unroll
        for (int i = 0; i < NQ; i++) ss += xq[i] * xq[i];
        float strength = sqrtf(ss);
        float gate = 1.0f / (1.0f + expf(-(strength - 0.05f)));

        #pragma unroll
        for (int r2 = 0; r2 < 2; r2++) {
            int j = lane + r2 * 32;
            float hv = b1[j];
            #pragma unroll
            for (int i = 0; i < NQ; i++) hv += xq[i] * w1[j * NQ + i];
            sh_h[b][j] = fmaxf(hv, 0.0f);
        }
        __syncwarp();
        #pragma unroll
        for (int r2 = 0; r2 < 2; r2++) {
            int o = lane + r2 * 32;
            float gv = b2[o];
            #pragma unroll 8
            for (int j = 0; j < OO; j++) gv += sh_h[b][j] * w2[o * OO + j];
            g_add[b * OO + o] = conv_b[o] + gate * gv;
        }
        const long long base = (long long)BB * OO * HW;
        if ((long long)out_size >= base + BB * NQ + BB) {
            if (lane < NQ) out[base + b * NQ + lane] = xq[lane];
            if (lane == 0) out[base + BB * NQ + b] = strength;
        }
    }
    __syncthreads();
    if (tid == 0) g_cnt = 0;
}

// ============ K_CONV: persistent tf32 mma.sync GEMM ========================
// out[b, o, px] = sum_c w[o,c] x[b,c,px] + g_add[b,o]
// Tile = 64 o x 128 px. 8 warps = 4(M) x 2(N-half of 64 px each).
// Weights split hi/lo (tf32), two MMA passes -> near-fp32 accuracy.
#define SM_WHI 0
#define SM_WLO 17408                    // 64 * 68 * 4
#define SM_STG 34816
#define SM_SZ  (34816 + 2 * 16 * 136 * 4)   // 52224 B

__global__ void __launch_bounds__(256, 2)
k_conv(const float* __restrict__ x, const float* __restrict__ conv_w,
       float* __restrict__ out) {
    extern __shared__ __align__(16) char sm[];
    uint32_t* whi = (uint32_t*)(sm + SM_WHI);     // [o][68] padded, tf32 hi
    uint32_t* wlo = (uint32_t*)(sm + SM_WLO);     // [o][68] padded, tf32 lo
    float*    stg = (float*)(sm + SM_STG);        // [2][16][136] padded
    const uint32_t stg_b = (uint32_t)__cvta_generic_to_shared(sm) + SM_STG;

    const int tid = threadIdx.x, wid = tid >> 5, lane = tid & 31;
    const int wm = wid & 3, wn = wid >> 2;        // warp M-group / N-half
    const int g = lane >> 2, tig = lane & 3;
    const int m0 = wm * 16;

    // prefetch of chunk (tile t, kc): 16 channels x 128 px = 512 x 16B
    auto prefetch = [&](int t, int kc, int buf) {
        const int b = t >> 9, px0 = (t & 511) << 7;
        const float* src = x + ((size_t)b * CC + kc * 16) * HW + px0;
        #pragma unroll
        for (int it = 0; it < 2; it++) {
            int e = tid + it * 256;
            int row = e >> 5, quad = e & 31;
            cp_async16(stg_b + (uint32_t)(buf * 8704 + row * 544 + quad * 16),
                       src + (size_t)row * HW + quad * 4);
        }
        cp_commit();
    };

    // issue first chunk before weight fill to hide DRAM latency
    if (blockIdx.x < NTILE) prefetch(blockIdx.x, 0, 0);

    for (int e = tid; e < OO * CC; e += 256) {
        int o = e >> 6, c = e & 63;
        float w = conv_w[o * CC + c];
        uint32_t hi = cvt_tf32(w);
        uint32_t lo = cvt_tf32(w - __uint_as_float(hi));
        whi[o * 68 + c] = hi;
        wlo[o * 68 + c] = lo;
    }
    __syncthreads();

    int cn = 0;
    for (int t = blockIdx.x; t < NTILE; t += gridDim.x) {
        float acc[8][4];
        #pragma unroll
        for (int j = 0; j < 8; j++)
            #pragma unroll
            for (int v = 0; v < 4; v++) acc[j][v] = 0.0f;

        #pragma unroll 1
        for (int kc = 0; kc < 4; kc++, cn++) {
            int nt = t, nkc = kc + 1;
            if (nkc == 4) { nt = t + gridDim.x; nkc = 0; }
            if (nt < NTILE) { prefetch(nt, nkc, (cn + 1) & 1); cp_wait<1>(); }
            else           { cp_wait<0>(); }
            __syncthreads();

            const float* xs = stg + (cn & 1) * 2176;   // this chunk
            #pragma unroll
            for (int ks = 0; ks < 2; ks++) {
                const int c0 = kc * 16 + ks * 8 + tig;
                uint32_t ahi[4], alo[4];
                ahi[0] = whi[(m0 + g) * 68 + c0];
                ahi[1] = whi[(m0 + g + 8) * 68 + c0];
                ahi[2] = whi[(m0 + g) * 68 + c0 + 4];
                ahi[3] = whi[(m0 + g + 8) * 68 + c0 + 4];
                alo[0] = wlo[(m0 + g) * 68 + c0];
                alo[1] = wlo[(m0 + g + 8) * 68 + c0];
                alo[2] = wlo[(m0 + g) * 68 + c0 + 4];
                alo[3] = wlo[(m0 + g + 8) * 68 + c0 + 4];
                const int r0 = ks * 8 + tig;
                #pragma unroll
                for (int j = 0; j < 8; j++) {
                    int col = wn * 64 + j * 8 + g;
                    uint32_t b0 = cvt_tf32(xs[r0 * 136 + col]);
                    uint32_t b1 = cvt_tf32(xs[(r0 + 4) * 136 + col]);
                    mma8(acc[j], ahi, b0, b1);
                    mma8(acc[j], alo, b0, b1);
                }
            }
            __syncthreads();
        }

        // epilogue: add bias+gate term, coalesced-sector float2 stores
        const int b = t >> 9, px0 = (t & 511) << 7;
        float add0 = g_add[b * OO + m0 + g];
        float add1 = g_add[b * OO + m0 + g + 8];
        float* o0 = out + ((size_t)(b * OO + m0 + g)) * HW + px0 + wn * 64;
        float* o1 = o0 + (size_t)8 * HW;
        #pragma unroll
        for (int j = 0; j < 8; j++) {
            *(float2*)(o0 + j * 8 + 2 * tig) = make_float2(acc[j][0] + add0, acc[j][1] + add0);
            *(float2*)(o1 + j * 8 + 2 * tig) = make_float2(acc[j][2] + add1, acc[j][3] + add1);
        }
    }
}

// ================= launch =================================================
extern "C" void kernel_launch(void* const* d_in, const int* in_sizes, int n_in,
                              void* d_out, int out_size) {
    const float* x      = (const float*)d_in[0];
    const float* cw     = (const float*)d_in[1];
    const float* qw     = (const float*)d_in[2];
    const float* w1     = (const float*)d_in[3];
    const float* b1     = (const float*)d_in[4];
    const float* w2     = (const float*)d_in[5];
    const float* b2     = (const float*)d_in[6];
    const float* conv_w = (const float*)d_in[7];
    const float* conv_b = (const float*)d_in[8];
    float* out = (float*)d_out;

    static int attr_done = 0;
    if (!attr_done) {
        cudaFuncSetAttribute(k_conv, cudaFuncAttributeMaxDynamicSharedMemorySize, SM_SZ);
        attr_done = 1;
    }
    k_pre<<<BB * NQ, 256>>>(x, cw, qw, w1, b1, w2, b2, conv_b, out, out_size);
    k_conv<<<GRID_CONV, 256, SM_SZ>>>(x, conv_w, out);
}

// round 6
// speedup vs baseline: 1.8327x; 1.1034x over previous
#include <cuda_runtime.h>
#include <math.h>
#include <stdint.h>

#define HW 65536
#define CC 64
#define OO 64
#define BB 16
#define NQ 8
#define PIF 3.14159265358979323846f
#define NTILE (BB * (HW / 128))   // 8192 tiles of 128 px
#define GRID_CONV 444             // 3 CTAs/SM * 148 SMs

__device__ float g_xg[BB * NQ];
__device__ float g_part[BB * NQ * 4];
__device__ float g_add[BB * OO];
__device__ int   g_cnt;

// ---------------- helpers ----------------
__device__ __forceinline__ uint32_t cvt_tf32(float f) {
    uint32_t r; asm("cvt.rna.tf32.f32 %0, %1;" : "=r"(r) : "f"(f)); return r;
}
__device__ __forceinline__ void cp_async16(uint32_t s, const float* g) {
    asm volatile("cp.async.cg.shared.global [%0], [%1], 16;\n"
                 :: "r"(s), "l"(__cvta_generic_to_global(g)));
}
__device__ __forceinline__ void cp_commit() { asm volatile("cp.async.commit_group;\n"); }
template <int N> __device__ __forceinline__ void cp_wait() {
    asm volatile("cp.async.wait_group %0;\n" :: "n"(N));
}
__device__ __forceinline__ void mma8(float* c, const uint32_t* a, uint32_t b0, uint32_t b1) {
    asm volatile("mma.sync.aligned.m16n8k8.row.col.f32.tf32.tf32.f32 "
                 "{%0,%1,%2,%3}, {%4,%5,%6,%7}, {%8,%9}, {%0,%1,%2,%3};"
                 : "+f"(c[0]), "+f"(c[1]), "+f"(c[2]), "+f"(c[3])
                 : "r"(a[0]), "r"(a[1]), "r"(a[2]), "r"(a[3]), "r"(b0), "r"(b1));
}

// ============ K_PRE: 8-channel means (4-way split) + quantum + MLP =========
__global__ void k_pre(const float* __restrict__ x,
                      const float* __restrict__ cw, const float* __restrict__ qw,
                      const float* __restrict__ w1, const float* __restrict__ b1,
                      const float* __restrict__ w2, const float* __restrict__ b2,
                      const float* __restrict__ conv_b,
                      float* __restrict__ out, int out_size) {
    const int tid = threadIdx.x;
    const int cid = blockIdx.x >> 2;          // (b,q) in [0,128)
    const int part = blockIdx.x & 3;          // quarter of the image
    const float4* p = reinterpret_cast<const float4*>(
        x + ((size_t)(cid >> 3) * CC + (cid & 7)) * HW + part * (HW / 4));
    float s = 0.0f;
    #pragma unroll 8
    for (int i = tid; i < HW / 16; i += 256) {
        float4 v = p[i];
        s += (v.x + v.y) + (v.z + v.w);
    }
    #pragma unroll
    for (int o = 16; o; o >>= 1) s += __shfl_xor_sync(0xffffffffu, s, o);
    __shared__ float ws[8];
    __shared__ int s_last;
    __shared__ float sh_h[BB][OO];
    if ((tid & 31) == 0) ws[tid >> 5] = s;
    __syncthreads();
    if (tid == 0) {
        float t = 0.0f;
        #pragma unroll
        for (int w = 0; w < 8; w++) t += ws[w];
        g_part[blockIdx.x] = t;
        __threadfence();
        s_last = (atomicAdd(&g_cnt, 1) == 4 * BB * NQ - 1) ? 1 : 0;
    }
    __syncthreads();
    if (!s_last) return;
    __threadfence();

    // combine partials
    if (tid < BB * NQ) {
        float t = g_part[tid * 4] + g_part[tid * 4 + 1] +
                  g_part[tid * 4 + 2] + g_part[tid * 4 + 3];
        g_xg[tid] = t * (1.0f / (float)HW);
    }
    __syncthreads();

    const int wid = tid >> 5, lane = tid & 31;
    for (int rep = 0; rep < 2; rep++) {
        const int b = wid + rep * 8;
        float xq[NQ];
        #pragma unroll
        for (int pr = 0; pr < 4; pr++) {
            int ia = 2 * pr, ib = 2 * pr + 1;
            float ta = PIF * (g_xg[b * 8 + ia] * cw[ia]) + qw[ia];
            float tb = PIF * (g_xg[b * 8 + ib] * cw[ib]) + qw[ib];
            float sa, ca, sb, cb;
            sincosf(ta * 0.5f, &sa, &ca);
            sincosf(tb * 0.5f, &sb, &cb);
            float psi00 = ca * cb, psi01 = ca * sb, psi10 = sa * sb, psi11 = sa * cb;
            float shA, chA, shB, chB;
            sincosf(qw[8 + ia] * 0.5f, &shA, &chA);
            sincosf(qw[8 + ib] * 0.5f, &shB, &chB);
            float m00 = chA * psi00 - shA * psi10, m01 = chA * psi01 - shA * psi11;
            float m10 = shA * psi00 + chA * psi10, m11 = shA * psi01 + chA * psi11;
            float q00 = m00 * chB - m01 * shB, q01 = m00 * shB + m01 * chB;
            float q10 = m10 * chB - m11 * shB, q11 = m10 * shB + m11 * chB;
            float p00 = q00 * q00, p01 = q01 * q01, p10 = q10 * q10, p11 = q11 * q11;
            xq[ia] = (p00 + p01) - (p10 + p11);
            xq[ib] = (p00 + p10) - (p01 + p11);
        }
        float ss = 0.0f;
        #pragma unroll
        for (int i = 0; i < NQ; i++) ss += xq[i] * xq[i];
        float strength = sqrtf(ss);
        float gate = 1.0f / (1.0f + expf(-(strength - 0.05f)));

        #pragma unroll
        for (int r2 = 0; r2 < 2; r2++) {
            int j = lane + r2 * 32;
            float hv = b1[j];
            #pragma unroll
            for (int i = 0; i < NQ; i++) hv += xq[i] * w1[j * NQ + i];
            sh_h[b][j] = fmaxf(hv, 0.0f);
        }
        __syncwarp();
        #pragma unroll
        for (int r2 = 0; r2 < 2; r2++) {
            int o = lane + r2 * 32;
            float gv = b2[o];
            #pragma unroll 8
            for (int j = 0; j < OO; j++) gv += sh_h[b][j] * w2[o * OO + j];
            g_add[b * OO + o] = conv_b[o] + gate * gv;
        }
        const long long base = (long long)BB * OO * HW;
        if ((long long)out_size >= base + BB * NQ + BB) {
            if (lane < NQ) out[base + b * NQ + lane] = xq[lane];
            if (lane == 0) out[base + BB * NQ + b] = strength;
        }
    }
    __syncthreads();
    if (tid == 0) g_cnt = 0;
}

// ============ K_CONV: persistent tf32 mma.sync GEMM, 3-slot ring ===========
// Tile = 64 o x 128 px. 8 warps = 4(M) x 2(N). Weights split hi/lo.
#define SM_WHI 0
#define SM_WLO 17408                       // 64 * 68 * 4
#define SM_STG 34816
#define SLOT_B 8704                        // 16 * 136 * 4
#define SM_SZ  (SM_STG + 3 * SLOT_B)       // 60928 B

__global__ void __launch_bounds__(256, 3)
k_conv(const float* __restrict__ x, const float* __restrict__ conv_w,
       float* __restrict__ out) {
    extern __shared__ __align__(16) char sm[];
    uint32_t* whi = (uint32_t*)(sm + SM_WHI);
    uint32_t* wlo = (uint32_t*)(sm + SM_WLO);
    float*    stg = (float*)(sm + SM_STG);
    const uint32_t stg_b = (uint32_t)__cvta_generic_to_shared(sm) + SM_STG;

    const int tid = threadIdx.x, lane = tid & 31, wid = tid >> 5;
    const int wm = wid & 3, wn = wid >> 2;
    const int g = lane >> 2, tig = lane & 3;
    const int m0 = wm * 16;

    // prefetch chunk m (global per-CTA chunk counter) into slot
    auto prefetch = [&](int m, int slot) {
        int t = blockIdx.x + (m >> 2) * gridDim.x;
        if (t < NTILE) {
            int b = t >> 9, px0 = (t & 511) << 7, kc = m & 3;
            const float* src = x + ((size_t)b * CC + kc * 16) * HW + px0;
            #pragma unroll
            for (int it = 0; it < 2; it++) {
                int e = tid + it * 256;
                int row = e >> 5, quad = e & 31;
                cp_async16(stg_b + (uint32_t)(slot * SLOT_B + row * 544 + quad * 16),
                           src + (size_t)row * HW + quad * 4);
            }
        }
        cp_commit();
    };

    prefetch(0, 0);
    prefetch(1, 1);

    for (int e = tid; e < OO * CC; e += 256) {
        int o = e >> 6, c = e & 63;
        float w = conv_w[o * CC + c];
        uint32_t hi = cvt_tf32(w);
        uint32_t lo = cvt_tf32(w - __uint_as_float(hi));
        whi[o * 68 + c] = hi;
        wlo[o * 68 + c] = lo;
    }
    __syncthreads();

    int cn = 0;
    for (int t = blockIdx.x; t < NTILE; t += gridDim.x) {
        float acc[8][4];
        #pragma unroll
        for (int j = 0; j < 8; j++)
            #pragma unroll
            for (int v = 0; v < 4; v++) acc[j][v] = 0.0f;

        #pragma unroll 1
        for (int kc = 0; kc < 4; kc++, cn++) {
            cp_wait<1>();             // chunk cn complete
            __syncthreads();          // slot (cn+2)%3 fully consumed by all
            prefetch(cn + 2, (cn + 2) % 3);

            const float* xs = stg + (cn % 3) * (SLOT_B / 4);
            #pragma unroll
            for (int ks = 0; ks < 2; ks++) {
                const int c0 = kc * 16 + ks * 8 + tig;
                uint32_t ahi[4], alo[4];
                ahi[0] = whi[(m0 + g) * 68 + c0];
                ahi[1] = whi[(m0 + g + 8) * 68 + c0];
                ahi[2] = whi[(m0 + g) * 68 + c0 + 4];
                ahi[3] = whi[(m0 + g + 8) * 68 + c0 + 4];
                alo[0] = wlo[(m0 + g) * 68 + c0];
                alo[1] = wlo[(m0 + g + 8) * 68 + c0];
                alo[2] = wlo[(m0 + g) * 68 + c0 + 4];
                alo[3] = wlo[(m0 + g + 8) * 68 + c0 + 4];
                const int r0 = ks * 8 + tig;
                #pragma unroll
                for (int j = 0; j < 8; j++) {
                    int col = wn * 64 + j * 8 + g;
                    uint32_t b0 = cvt_tf32(xs[r0 * 136 + col]);
                    uint32_t b1 = cvt_tf32(xs[(r0 + 4) * 136 + col]);
                    mma8(acc[j], ahi, b0, b1);
                    mma8(acc[j], alo, b0, b1);
                }
            }
        }

        const int b = t >> 9, px0 = (t & 511) << 7;
        float add0 = g_add[b * OO + m0 + g];
        float add1 = g_add[b * OO + m0 + g + 8];
        float* o0 = out + ((size_t)(b * OO + m0 + g)) * HW + px0 + wn * 64;
        float* o1 = o0 + (size_t)8 * HW;
        #pragma unroll
        for (int j = 0; j < 8; j++) {
            *(float2*)(o0 + j * 8 + 2 * tig) = make_float2(acc[j][0] + add0, acc[j][1] + add0);
            *(float2*)(o1 + j * 8 + 2 * tig) = make_float2(acc[j][2] + add1, acc[j][3] + add1);
        }
    }
}

// ================= launch =================================================
extern "C" void kernel_launch(void* const* d_in, const int* in_sizes, int n_in,
                              void* d_out, int out_size) {
    const float* x      = (const float*)d_in[0];
    const float* cw     = (const float*)d_in[1];
    const float* qw     = (const float*)d_in[2];
    const float* w1     = (const float*)d_in[3];
    const float* b1     = (const float*)d_in[4];
    const float* w2     = (const float*)d_in[5];
    const float* b2     = (const float*)d_in[6];
    const float* conv_w = (const float*)d_in[7];
    const float* conv_b = (const float*)d_in[8];
    float* out = (float*)d_out;

    static int attr_done = 0;
    if (!attr_done) {
        cudaFuncSetAttribute(k_conv, cudaFuncAttributeMaxDynamicSharedMemorySize, SM_SZ);
        attr_done = 1;
    }
    k_pre<<<BB * NQ * 4, 256>>>(x, cw, qw, w1, b1, w2, b2, conv_b, out, out_size);
    k_conv<<<GRID_CONV, 256, SM_SZ>>>(x, conv_w, out);
}

// round 7
// speedup vs baseline: 2.0709x; 1.1300x over previous
#include <cuda_runtime.h>
#include <math.h>
#include <stdint.h>

#define HW 65536
#define CC 64
#define OO 64
#define BB 16
#define NQ 8
#define PIF 3.14159265358979323846f
#define NTILE (BB * (HW / 128))   // 8192 tiles of 128 px
#define GRID_CONV 592             // 4 CTAs/SM * 148 SMs

__device__ float g_xg[BB * NQ];
__device__ float g_part[BB * NQ * 4];
__device__ float g_add[BB * OO];
__device__ int   g_cnt;

// ---------------- helpers ----------------
__device__ __forceinline__ uint32_t cvt_tf32(float f) {
    uint32_t r; asm("cvt.rna.tf32.f32 %0, %1;" : "=r"(r) : "f"(f)); return r;
}
__device__ __forceinline__ void cp_async16(uint32_t s, const float* g) {
    asm volatile("cp.async.cg.shared.global [%0], [%1], 16;\n"
                 :: "r"(s), "l"(__cvta_generic_to_global(g)));
}
__device__ __forceinline__ void cp_commit() { asm volatile("cp.async.commit_group;\n"); }
template <int N> __device__ __forceinline__ void cp_wait() {
    asm volatile("cp.async.wait_group %0;\n" :: "n"(N));
}
__device__ __forceinline__ void mma8(float* c, const uint32_t* a, uint32_t b0, uint32_t b1) {
    asm volatile("mma.sync.aligned.m16n8k8.row.col.f32.tf32.tf32.f32 "
                 "{%0,%1,%2,%3}, {%4,%5,%6,%7}, {%8,%9}, {%0,%1,%2,%3};"
                 : "+f"(c[0]), "+f"(c[1]), "+f"(c[2]), "+f"(c[3])
                 : "r"(a[0]), "r"(a[1]), "r"(a[2]), "r"(a[3]), "r"(b0), "r"(b1));
}

// ============ K_PRE: 8-channel means (4-way split) + quantum + MLP =========
__global__ void k_pre(const float* __restrict__ x,
                      const float* __restrict__ cw, const float* __restrict__ qw,
                      const float* __restrict__ w1, const float* __restrict__ b1,
                      const float* __restrict__ w2, const float* __restrict__ b2,
                      const float* __restrict__ conv_b,
                      float* __restrict__ out, int out_size) {
    const int tid = threadIdx.x;
    const int cid = blockIdx.x >> 2;
    const int part = blockIdx.x & 3;
    const float4* p = reinterpret_cast<const float4*>(
        x + ((size_t)(cid >> 3) * CC + (cid & 7)) * HW + part * (HW / 4));
    float s = 0.0f;
    #pragma unroll 8
    for (int i = tid; i < HW / 16; i += 256) {
        float4 v = p[i];
        s += (v.x + v.y) + (v.z + v.w);
    }
    #pragma unroll
    for (int o = 16; o; o >>= 1) s += __shfl_xor_sync(0xffffffffu, s, o);
    __shared__ float ws[8];
    __shared__ int s_last;
    __shared__ float sh_h[BB][OO];
    if ((tid & 31) == 0) ws[tid >> 5] = s;
    __syncthreads();
    if (tid == 0) {
        float t = 0.0f;
        #pragma unroll
        for (int w = 0; w < 8; w++) t += ws[w];
        g_part[blockIdx.x] = t;
        __threadfence();
        s_last = (atomicAdd(&g_cnt, 1) == 4 * BB * NQ - 1) ? 1 : 0;
    }
    __syncthreads();
    if (!s_last) return;
    __threadfence();

    if (tid < BB * NQ) {
        float t = g_part[tid * 4] + g_part[tid * 4 + 1] +
                  g_part[tid * 4 + 2] + g_part[tid * 4 + 3];
        g_xg[tid] = t * (1.0f / (float)HW);
    }
    __syncthreads();

    const int wid = tid >> 5, lane = tid & 31;
    for (int rep = 0; rep < 2; rep++) {
        const int b = wid + rep * 8;
        float xq[NQ];
        #pragma unroll
        for (int pr = 0; pr < 4; pr++) {
            int ia = 2 * pr, ib = 2 * pr + 1;
            float ta = PIF * (g_xg[b * 8 + ia] * cw[ia]) + qw[ia];
            float tb = PIF * (g_xg[b * 8 + ib] * cw[ib]) + qw[ib];
            float sa, ca, sb, cb;
            sincosf(ta * 0.5f, &sa, &ca);
            sincosf(tb * 0.5f, &sb, &cb);
            float psi00 = ca * cb, psi01 = ca * sb, psi10 = sa * sb, psi11 = sa * cb;
            float shA, chA, shB, chB;
            sincosf(qw[8 + ia] * 0.5f, &shA, &chA);
            sincosf(qw[8 + ib] * 0.5f, &shB, &chB);
            float m00 = chA * psi00 - shA * psi10, m01 = chA * psi01 - shA * psi11;
            float m10 = shA * psi00 + chA * psi10, m11 = shA * psi01 + chA * psi11;
            float q00 = m00 * chB - m01 * shB, q01 = m00 * shB + m01 * chB;
            float q10 = m10 * chB - m11 * shB, q11 = m10 * shB + m11 * chB;
            float p00 = q00 * q00, p01 = q01 * q01, p10 = q10 * q10, p11 = q11 * q11;
            xq[ia] = (p00 + p01) - (p10 + p11);
            xq[ib] = (p00 + p10) - (p01 + p11);
        }
        float ss = 0.0f;
        #pragma unroll
        for (int i = 0; i < NQ; i++) ss += xq[i] * xq[i];
        float strength = sqrtf(ss);
        float gate = 1.0f / (1.0f + expf(-(strength - 0.05f)));

        #pragma unroll
        for (int r2 = 0; r2 < 2; r2++) {
            int j = lane + r2 * 32;
            float hv = b1[j];
            #pragma unroll
            for (int i = 0; i < NQ; i++) hv += xq[i] * w1[j * NQ + i];
            sh_h[b][j] = fmaxf(hv, 0.0f);
        }
        __syncwarp();
        #pragma unroll
        for (int r2 = 0; r2 < 2; r2++) {
            int o = lane + r2 * 32;
            float gv = b2[o];
            #pragma unroll 8
            for (int j = 0; j < OO; j++) gv += sh_h[b][j] * w2[o * OO + j];
            g_add[b * OO + o] = conv_b[o] + gate * gv;
        }
        const long long base = (long long)BB * OO * HW;
        if ((long long)out_size >= base + BB * NQ + BB) {
            if (lane < NQ) out[base + b * NQ + lane] = xq[lane];
            if (lane == 0) out[base + BB * NQ + b] = strength;
        }
    }
    __syncthreads();
    if (tid == 0) g_cnt = 0;
}

// ============ K_CONV: persistent tf32 mma.sync GEMM, single pass ===========
// Tile = 64 o x 128 px. 8 warps = 4(M) x 2(N). 3-slot staging ring.
#define SM_W   0
#define SM_STG 17408                       // 64 * 68 * 4
#define SLOT_B 8704                        // 16 * 136 * 4
#define SM_SZ  (SM_STG + 3 * SLOT_B)       // 43520 B

__global__ void __launch_bounds__(256, 4)
k_conv(const float* __restrict__ x, const float* __restrict__ conv_w,
       float* __restrict__ out) {
    extern __shared__ __align__(16) char sm[];
    uint32_t* whi = (uint32_t*)(sm + SM_W);
    float*    stg = (float*)(sm + SM_STG);
    const uint32_t stg_b = (uint32_t)__cvta_generic_to_shared(sm) + SM_STG;

    const int tid = threadIdx.x, lane = tid & 31, wid = tid >> 5;
    const int wm = wid & 3, wn = wid >> 2;
    const int g = lane >> 2, tig = lane & 3;
    const int m0 = wm * 16;

    auto prefetch = [&](int m, int slot) {
        int t = blockIdx.x + (m >> 2) * gridDim.x;
        if (t < NTILE) {
            int b = t >> 9, px0 = (t & 511) << 7, kc = m & 3;
            const float* src = x + ((size_t)b * CC + kc * 16) * HW + px0;
            #pragma unroll
            for (int it = 0; it < 2; it++) {
                int e = tid + it * 256;
                int row = e >> 5, quad = e & 31;
                cp_async16(stg_b + (uint32_t)(slot * SLOT_B + row * 544 + quad * 16),
                           src + (size_t)row * HW + quad * 4);
            }
        }
        cp_commit();
    };

    prefetch(0, 0);
    prefetch(1, 1);

    for (int e = tid; e < OO * CC; e += 256) {
        int o = e >> 6, c = e & 63;
        whi[o * 68 + c] = cvt_tf32(conv_w[o * CC + c]);
    }
    __syncthreads();

    int cn = 0;
    for (int t = blockIdx.x; t < NTILE; t += gridDim.x) {
        float acc[8][4];
        #pragma unroll
        for (int j = 0; j < 8; j++)
            #pragma unroll
            for (int v = 0; v < 4; v++) acc[j][v] = 0.0f;

        #pragma unroll 1
        for (int kc = 0; kc < 4; kc++, cn++) {
            cp_wait<1>();             // chunk cn complete
            __syncthreads();          // slot (cn+2)%3 fully consumed by all
            prefetch(cn + 2, (cn + 2) % 3);

            const float* xs = stg + (cn % 3) * (SLOT_B / 4);
            #pragma unroll
            for (int ks = 0; ks < 2; ks++) {
                const int c0 = kc * 16 + ks * 8 + tig;
                uint32_t a[4];
                a[0] = whi[(m0 + g) * 68 + c0];
                a[1] = whi[(m0 + g + 8) * 68 + c0];
                a[2] = whi[(m0 + g) * 68 + c0 + 4];
                a[3] = whi[(m0 + g + 8) * 68 + c0 + 4];
                const int r0 = ks * 8 + tig;
                #pragma unroll
                for (int j = 0; j < 8; j++) {
                    int col = wn * 64 + j * 8 + g;
                    uint32_t b0 = cvt_tf32(xs[r0 * 136 + col]);
                    uint32_t b1 = cvt_tf32(xs[(r0 + 4) * 136 + col]);
                    mma8(acc[j], a, b0, b1);
                }
            }
        }

        const int b = t >> 9, px0 = (t & 511) << 7;
        float add0 = g_add[b * OO + m0 + g];
        float add1 = g_add[b * OO + m0 + g + 8];
        float* o0 = out + ((size_t)(b * OO + m0 + g)) * HW + px0 + wn * 64;
        float* o1 = o0 + (size_t)8 * HW;
        #pragma unroll
        for (int j = 0; j < 8; j++) {
            *(float2*)(o0 + j * 8 + 2 * tig) = make_float2(acc[j][0] + add0, acc[j][1] + add0);
            *(float2*)(o1 + j * 8 + 2 * tig) = make_float2(acc[j][2] + add1, acc[j][3] + add1);
        }
    }
}

// ================= launch =================================================
extern "C" void kernel_launch(void* const* d_in, const int* in_sizes, int n_in,
                              void* d_out, int out_size) {
    const float* x      = (const float*)d_in[0];
    const float* cw     = (const float*)d_in[1];
    const float* qw     = (const float*)d_in[2];
    const float* w1     = (const float*)d_in[3];
    const float* b1     = (const float*)d_in[4];
    const float* w2     = (const float*)d_in[5];
    const float* b2     = (const float*)d_in[6];
    const float* conv_w = (const float*)d_in[7];
    const float* conv_b = (const float*)d_in[8];
    float* out = (float*)d_out;

    cudaFuncSetAttribute(k_conv, cudaFuncAttributeMaxDynamicSharedMemorySize, SM_SZ);
    k_pre<<<BB * NQ * 4, 256>>>(x, cw, qw, w1, b1, w2, b2, conv_b, out, out_size);
    k_conv<<<GRID_CONV, 256, SM_SZ>>>(x, conv_w, out);
}